// round 1
// baseline (speedup 1.0000x reference)
#include <cuda_runtime.h>
#include <cuda_bf16.h>

// Problem constants
#define BB 128
#define FHH 26
#define FWW 26
#define TT 50
#define AA 5
#define NCLS 20
#define KK (FHH*FWW)          // 676
#define KA (KK*AA)            // 3380
#define CH (5+NCLS)           // 25
#define IGNORE_T 0.75f
#define OBJ_SCALE 5.0f

#define PARTS 4
#define APP ((KA + PARTS - 1)/PARTS)   // 845 anchors per part
#define THR 256
#define BMW ((KA + 31)/32)             // 106 bitmap words

__constant__ float c_aw[AA] = {1.3221f, 3.19275f, 5.05587f, 9.47112f, 11.2364f};
__constant__ float c_ah[AA] = {1.73145f, 4.00944f, 8.09892f, 4.84053f, 10.0071f};

// Scratch (no allocation allowed)
__device__ float4 g_gt[BB][TT];       // scaled xxyy (sanitized if invalid)
__device__ float  g_ga[BB][TT];       // gt area
__device__ int    g_slot[BB][TT];     // final assignment slot (k*A+a) or -1
__device__ float4 g_tb[BB][TT];       // target box (dx, dy, w-ratio, h-ratio)
__device__ int    g_cls[BB][TT];      // class index
__device__ float4 g_part[BB][PARTS];  // (sumA, sumB, sumAsg, posAny)

__device__ __forceinline__ float sigmoidf_(float x) {
    return 1.0f / (1.0f + __expf(-x));
}

// ---------------------------------------------------------------------------
// Phase A: per-(batch, gt) assignment. One block per batch, 64 threads.
// ---------------------------------------------------------------------------
__global__ __launch_bounds__(64)
void phaseA(const float* __restrict__ targets) {
    const int b = blockIdx.x;
    const int t = threadIdx.x;

    __shared__ int s_slot[TT];
    __shared__ int s_valid[TT];

    if (t < TT) {
        const float* g = targets + ((size_t)b * TT + t) * 5;
        float x1 = g[0], y1 = g[1], x2 = g[2], y2 = g[3], cl = g[4];
        bool valid = (x1 + y1 + x2 + y2) > 0.0f;

        float gx1 = x1 * FWW, gy1 = y1 * FHH, gx2 = x2 * FWW, gy2 = y2 * FHH;
        float gcx = 0.5f * (gx1 + gx2), gcy = 0.5f * (gy1 + gy2);
        float gw = gx2 - gx1, gh = gy2 - gy1;
        float garea = gw * gh;

        int cx = min(max((int)floorf(gcx), 0), FWW - 1);
        int cy = min(max((int)floorf(gcy), 0), FHH - 1);
        int cell = cy * FWW + cx;

        // argmax over 5 anchor boxes centered at (cx+0.5, cy+0.5);
        // strict > keeps first occurrence, matching jnp.argmax
        float acx = (float)cx + 0.5f, acy = (float)cy + 0.5f;
        float best = -1e30f;
        int aidx = 0;
        #pragma unroll
        for (int a = 0; a < AA; a++) {
            float aw = c_aw[a], ah = c_ah[a];
            float ax1 = acx - 0.5f * aw, ax2 = acx + 0.5f * aw;
            float ay1 = acy - 0.5f * ah, ay2 = acy + 0.5f * ah;
            float xi1 = fmaxf(ax1, gx1), yi1 = fmaxf(ay1, gy1);
            float xi2 = fminf(ax2, gx2), yi2 = fminf(ay2, gy2);
            float inter = fmaxf(xi2 - xi1, 0.0f) * fmaxf(yi2 - yi1, 0.0f);
            float iou = inter / (aw * ah + garea - inter);
            if (iou > best) { best = iou; aidx = a; }
        }

        if (valid) {
            g_gt[b][t] = make_float4(gx1, gy1, gx2, gy2);
            g_ga[b][t] = garea;
        } else {
            // sanitized: never intersects, never wins the ratio compare
            g_gt[b][t] = make_float4(1e8f, 1e8f, 1e8f, 1e8f);
            g_ga[b][t] = 0.0f;
        }
        g_tb[b][t]  = make_float4(gcx - (float)cx, gcy - (float)cy,
                                  gw / c_aw[aidx], gh / c_ah[aidx]);
        g_cls[b][t] = (int)cl;

        s_slot[t]  = cell * AA + aidx;
        s_valid[t] = valid ? 1 : 0;
    }
    __syncthreads();

    if (t < TT) {
        // sequential-overwrite semantics: keep t only if no LATER valid t'
        // writes the same slot
        int slot = s_slot[t];
        bool fin = (s_valid[t] != 0);
        if (fin) {
            for (int t2 = t + 1; t2 < TT; t2++)
                if (s_valid[t2] && s_slot[t2] == slot) { fin = false; break; }
        }
        g_slot[b][t] = fin ? slot : -1;
    }
}

// ---------------------------------------------------------------------------
// Phase B: per-anchor losses. Grid (B, PARTS), THR threads.
// ---------------------------------------------------------------------------
__global__ __launch_bounds__(THR)
void phaseB(const float* __restrict__ outputs) {
    const int b    = blockIdx.x;
    const int part = blockIdx.y;
    const int tid  = threadIdx.x;

    __shared__ float4   s_gt[TT];
    __shared__ float    s_ga[TT];
    __shared__ int      s_slot[TT];
    __shared__ float4   s_tb[TT];
    __shared__ int      s_cls[TT];
    __shared__ unsigned s_bm[BMW];

    for (int i = tid; i < BMW; i += THR) s_bm[i] = 0u;
    if (tid < TT) {
        s_gt[tid]   = g_gt[b][tid];
        s_ga[tid]   = g_ga[b][tid];
        s_slot[tid] = g_slot[b][tid];
        s_tb[tid]   = g_tb[b][tid];
        s_cls[tid]  = g_cls[b][tid];
    }
    __syncthreads();
    if (tid < TT && s_slot[tid] >= 0)
        atomicOr(&s_bm[s_slot[tid] >> 5], 1u << (s_slot[tid] & 31));
    __syncthreads();

    const float* ob = outputs + (size_t)b * CH * KA;  // b * 125 * 676

    float sumA = 0.0f, sumB = 0.0f, sumAsg = 0.0f;
    int posAny = 0;

    const int lo = part * APP;
    const int hi = min(lo + APP, KA);
    for (int idx = lo + tid; idx < hi; idx += THR) {
        // idx = a*K + k for coalesced channel loads
        int a = idx / KK;
        int k = idx - a * KK;
        int yy = k / FWW, xx = k - yy * FWW;

        const float* p = ob + (size_t)(a * CH) * KK + k;
        float tx = p[0],       ty = p[KK];
        float tw = p[2 * KK],  th = p[3 * KK];
        float tc = p[4 * KK];

        float sx = sigmoidf_(tx), sy = sigmoidf_(ty);
        float ew = __expf(tw),    eh = __expf(th);
        float conf = sigmoidf_(tc);

        float pcx = (float)xx + sx, pcy = (float)yy + sy;
        float pw = c_aw[a] * ew,    ph = c_ah[a] * eh;
        float px1 = pcx - 0.5f * pw, px2 = pcx + 0.5f * pw;
        float py1 = pcy - 0.5f * ph, py2 = pcy + 0.5f * ph;
        float pa = pw * ph;

        // division-free running max of inter/den over 50 gts
        float bi = 0.0f, bd = 1.0f;
        #pragma unroll 5
        for (int t = 0; t < TT; t++) {
            float4 g = s_gt[t];
            float xi1 = fmaxf(px1, g.x), yi1 = fmaxf(py1, g.y);
            float xi2 = fminf(px2, g.z), yi2 = fminf(py2, g.w);
            float inter = fmaxf(xi2 - xi1, 0.0f) * fmaxf(yi2 - yi1, 0.0f);
            float den = (pa + s_ga[t]) - inter;
            // inter/den > bi/bd  <=>  inter*bd > bi*den  (den,bd > 0)
            bool win = (inter * bd > bi * den);
            bi = win ? inter : bi;
            bd = win ? den   : bd;
        }
        float miou = bi / bd;   // == max IoU (>=0) if any valid gt, else 0
        // (when no valid gt the reference gives -1; both are < thresholds and
        //  unused otherwise, so downstream behavior is identical)

        if (miou > IGNORE_T) posAny = 1;

        int slot = k * AA + a;
        bool asg = (s_bm[slot >> 5] >> (slot & 31)) & 1u;
        if (asg) {
            int tt = 0;
            for (int t = 0; t < TT; t++) if (s_slot[t] == slot) tt = t;
            float4 tb = s_tb[tt];
            float d0 = sx - tb.x, d1 = sy - tb.y, d2 = ew - tb.z, d3 = eh - tb.w;
            sumAsg += 0.5f * (d0*d0 + d1*d1 + d2*d2 + d3*d3);   // COORD=1
            float di = OBJ_SCALE * conf - OBJ_SCALE * miou;
            sumAsg += 0.5f * di * di;
            // class CE = logsumexp - logit[cls]
            float lmax = -1e30f;
            #pragma unroll
            for (int c = 0; c < NCLS; c++) lmax = fmaxf(lmax, p[(5 + c) * KK]);
            float se = 0.0f;
            #pragma unroll
            for (int c = 0; c < NCLS; c++) se += __expf(p[(5 + c) * KK] - lmax);
            float lse = lmax + __logf(se);
            sumAsg += (lse - p[(5 + s_cls[tt]) * KK]);          // CLASS=1
        } else {
            float c2 = conf * conf;
            sumA += c2;
            if (miou >= IGNORE_T) sumB += c2;
        }
    }

    // block reduction (deterministic order within block)
    float pAf = (float)posAny;
    #pragma unroll
    for (int o = 16; o > 0; o >>= 1) {
        sumA   += __shfl_down_sync(0xffffffffu, sumA,   o);
        sumB   += __shfl_down_sync(0xffffffffu, sumB,   o);
        sumAsg += __shfl_down_sync(0xffffffffu, sumAsg, o);
        pAf    += __shfl_down_sync(0xffffffffu, pAf,    o);
    }
    __shared__ float rA[THR/32], rB[THR/32], rG[THR/32], rP[THR/32];
    int w = tid >> 5, l = tid & 31;
    if (l == 0) { rA[w] = sumA; rB[w] = sumB; rG[w] = sumAsg; rP[w] = pAf; }
    __syncthreads();
    if (tid == 0) {
        float a0 = 0, b0 = 0, g0 = 0, p0 = 0;
        #pragma unroll
        for (int i = 0; i < THR/32; i++) { a0 += rA[i]; b0 += rB[i]; g0 += rG[i]; p0 += rP[i]; }
        g_part[b][part] = make_float4(a0, b0, g0, p0);
    }
}

// ---------------------------------------------------------------------------
// Finalize: combine parts per batch, apply pos_any, sum over batches, /B.
// ---------------------------------------------------------------------------
__global__ __launch_bounds__(BB)
void finalize(float* __restrict__ out) {
    const int b = threadIdx.x;
    float sA = 0, sB = 0, sG = 0, sP = 0;
    #pragma unroll
    for (int p = 0; p < PARTS; p++) {
        float4 v = g_part[b][p];
        sA += v.x; sB += v.y; sG += v.z; sP += v.w;
    }
    bool pos = sP > 0.0f;
    float loss = 0.5f * (sA - (pos ? sB : 0.0f)) + sG;

    __shared__ float red[BB];
    red[b] = loss;
    __syncthreads();
    #pragma unroll
    for (int s = BB / 2; s > 0; s >>= 1) {
        if (b < s) red[b] += red[b + s];
        __syncthreads();
    }
    if (b == 0) out[0] = red[0] / (float)BB;
}

// ---------------------------------------------------------------------------
extern "C" void kernel_launch(void* const* d_in, const int* in_sizes, int n_in,
                              void* d_out, int out_size) {
    const float* outputs = (const float*)d_in[0];
    const float* targets = (const float*)d_in[1];
    if (n_in >= 2 && in_sizes[0] < in_sizes[1]) {  // defensive: order by size
        outputs = (const float*)d_in[1];
        targets = (const float*)d_in[0];
    }
    float* out = (float*)d_out;

    phaseA<<<BB, 64>>>(targets);
    dim3 gridB(BB, PARTS);
    phaseB<<<gridB, THR>>>(outputs);
    finalize<<<1, BB>>>(out);
}

// round 2
// speedup vs baseline: 1.3939x; 1.3939x over previous
#include <cuda_runtime.h>
#include <cuda_bf16.h>

// Problem constants
#define BB 128
#define FHH 26
#define FWW 26
#define TT 50
#define AA 5
#define NCLS 20
#define KK (FHH*FWW)          // 676
#define KA (KK*AA)            // 3380
#define CH (5+NCLS)           // 25
#define OBJ_SCALE 5.0f

#define PARTS 4
#define APP (KA/PARTS)        // 845 anchors per streaming part
#define THR 256
#define NA 4                  // anchors per thread (register-blocked)

__constant__ float c_aw[AA] = {1.3221f, 3.19275f, 5.05587f, 9.47112f, 11.2364f};
__constant__ float c_ah[AA] = {1.73145f, 4.00944f, 8.09892f, 4.84053f, 10.0071f};

// Scratch
__device__ float4 g_part[BB][PARTS + 1];  // streaming: (sumAll, sumFlag, 0, posAny)
                                          // part 4:   (corrA,  corrB,  asgLoss, 0)

__device__ __forceinline__ float sigmoidf_(float x) {
    return 1.0f / (1.0f + __expf(-x));
}

struct Pred {
    float px1, py1, px2, py2;  // corners
    float pa, pa3;             // area, 3*area
    float c2;                  // conf^2
    float sx, sy, ew, eh, conf;
};

// Shared decode so streaming and part-4 produce bitwise-identical values.
__device__ __forceinline__ Pred decode_anchor(const float* __restrict__ ob,
                                              int a, int k) {
    int yy = k / FWW, xx = k - yy * FWW;
    const float* p = ob + (size_t)(a * CH) * KK + k;
    Pred r;
    float tx = p[0], ty = p[KK], tw = p[2 * KK], th = p[3 * KK], tc = p[4 * KK];
    r.sx = sigmoidf_(tx);
    r.sy = sigmoidf_(ty);
    r.ew = __expf(tw);
    r.eh = __expf(th);
    r.conf = sigmoidf_(tc);
    float pw = c_aw[a] * r.ew, ph = c_ah[a] * r.eh;
    float pcx = (float)xx + r.sx, pcy = (float)yy + r.sy;
    r.px1 = pcx - 0.5f * pw; r.px2 = pcx + 0.5f * pw;
    r.py1 = pcy - 0.5f * ph; r.py2 = pcy + 0.5f * ph;
    r.pa  = pw * ph;
    r.pa3 = 3.0f * r.pa;
    r.c2  = r.conf * r.conf;
    return r;
}

__device__ __forceinline__ float inter_box(float px1, float py1, float px2,
                                           float py2, float4 g) {
    float dx = fminf(px2, g.z) - fmaxf(px1, g.x);
    float dy = fminf(py2, g.w) - fmaxf(py1, g.y);
    return fmaxf(dx, 0.0f) * fmaxf(dy, 0.0f);
}

// ---------------------------------------------------------------------------
// Fused main kernel: grid (B, PARTS+1).
//   blockIdx.y < PARTS : stream 845 anchors, emit (sumAll, sumFlag, 0, posAny)
//   blockIdx.y == PARTS: assignment + assigned-anchor losses + corrections
// ---------------------------------------------------------------------------
__global__ __launch_bounds__(THR)
void mainKernel(const float* __restrict__ outputs,
                const float* __restrict__ targets) {
    const int b    = blockIdx.x;
    const int part = blockIdx.y;
    const int tid  = threadIdx.x;

    __shared__ float4 s_gt[TT];    // scaled xxyy (sanitized if invalid)
    __shared__ float  s_mga3[TT];  // -3 * gt area
    __shared__ float  s_ga[TT];    // gt area
    // part-4 only
    __shared__ int    s_slot[TT];
    __shared__ int    s_valid[TT];
    __shared__ float4 s_tb[TT];
    __shared__ int    s_cls[TT];

    // ---- prolog: gt boxes (all parts) + assignment data (part 4) ----
    if (tid < TT) {
        const float* g = targets + ((size_t)b * TT + tid) * 5;
        float x1 = g[0], y1 = g[1], x2 = g[2], y2 = g[3], cl = g[4];
        bool valid = (x1 + y1 + x2 + y2) > 0.0f;

        float gx1 = x1 * FWW, gy1 = y1 * FHH, gx2 = x2 * FWW, gy2 = y2 * FHH;
        float gw = gx2 - gx1, gh = gy2 - gy1;
        float ga = gw * gh;

        if (valid) {
            s_gt[tid] = make_float4(gx1, gy1, gx2, gy2);
            s_ga[tid] = ga;
            s_mga3[tid] = -3.0f * ga;
        } else {
            s_gt[tid] = make_float4(1e8f, 1e8f, 1e8f, 1e8f);
            s_ga[tid] = 0.0f;
            s_mga3[tid] = 0.0f;
        }

        if (part == PARTS) {
            float gcx = 0.5f * (gx1 + gx2), gcy = 0.5f * (gy1 + gy2);
            int cx = min(max((int)floorf(gcx), 0), FWW - 1);
            int cy = min(max((int)floorf(gcy), 0), FHH - 1);
            int cell = cy * FWW + cx;

            float acx = (float)cx + 0.5f, acy = (float)cy + 0.5f;
            float best = -1e30f;
            int aidx = 0;
            #pragma unroll
            for (int a = 0; a < AA; a++) {
                float aw = c_aw[a], ah = c_ah[a];
                float ax1 = acx - 0.5f * aw, ax2 = acx + 0.5f * aw;
                float ay1 = acy - 0.5f * ah, ay2 = acy + 0.5f * ah;
                float xi1 = fmaxf(ax1, gx1), yi1 = fmaxf(ay1, gy1);
                float xi2 = fminf(ax2, gx2), yi2 = fminf(ay2, gy2);
                float inter = fmaxf(xi2 - xi1, 0.0f) * fmaxf(yi2 - yi1, 0.0f);
                float iou = inter / (aw * ah + ga - inter);
                if (iou > best) { best = iou; aidx = a; }
            }
            s_tb[tid]   = make_float4(gcx - (float)cx, gcy - (float)cy,
                                      gw / c_aw[aidx], gh / c_ah[aidx]);
            s_cls[tid]  = (int)cl;
            s_slot[tid] = cell * AA + aidx;
            s_valid[tid] = valid ? 1 : 0;
        }
    }
    __syncthreads();

    const float* ob = outputs + (size_t)b * CH * KA;

    float r0 = 0.0f, r1 = 0.0f, r2 = 0.0f, r3 = 0.0f;  // reduction payload

    if (part < PARTS) {
        // -------------------- streaming part --------------------
        const int lo = part * APP;
        const int base = lo + tid;

        Pred P[NA];
        bool v[NA];
        #pragma unroll
        for (int j = 0; j < NA; j++) {
            int idx = base + j * THR;
            v[j] = idx < lo + APP;
            int ci = v[j] ? idx : lo;
            int a = ci / KK;
            int k = ci - a * KK;
            P[j] = decode_anchor(ob, a, k);
        }

        float acc[NA];
        #pragma unroll
        for (int j = 0; j < NA; j++) acc[j] = 0.0f;

        #pragma unroll 5
        for (int t = 0; t < TT; t++) {
            float4 g = s_gt[t];
            float mg = s_mga3[t];
            #pragma unroll
            for (int j = 0; j < NA; j++) {
                float inter = inter_box(P[j].px1, P[j].py1, P[j].px2, P[j].py2, g);
                acc[j] = fmaxf(acc[j], fmaf(7.0f, inter, mg));
            }
        }

        float posAny = 0.0f;
        #pragma unroll
        for (int j = 0; j < NA; j++) {
            if (v[j]) {
                r0 += P[j].c2;                        // sumAll
                if (acc[j] >= P[j].pa3) r1 += P[j].c2; // sumFlag (iou >= 0.75)
                if (acc[j] >  P[j].pa3) posAny = 1.0f; // strict (iou > 0.75)
            }
        }
        r3 = posAny;
    } else {
        // -------------------- assignment part --------------------
        // dedup: keep t only if no LATER valid t' writes the same slot
        __shared__ int s_fslot[TT];
        if (tid < TT) {
            int slot = s_slot[tid];
            bool fin = (s_valid[tid] != 0);
            if (fin) {
                for (int t2 = tid + 1; t2 < TT; t2++)
                    if (s_valid[t2] && s_slot[t2] == slot) { fin = false; break; }
            }
            s_fslot[tid] = fin ? slot : -1;
        }
        __syncthreads();

        if (tid < TT && s_fslot[tid] >= 0) {
            int slot = s_fslot[tid];
            int k = slot / AA, a = slot - k * AA;
            Pred P = decode_anchor(ob, a, k);

            // exact max-IoU (division-free running max) + algebraic flag
            float bi = 0.0f, bd = 1.0f, acc = 0.0f;
            for (int t = 0; t < TT; t++) {
                float4 g = s_gt[t];
                float inter = inter_box(P.px1, P.py1, P.px2, P.py2, g);
                float den = P.pa + s_ga[t] - inter;
                bool win = (inter * bd > bi * den);
                bi = win ? inter : bi;
                bd = win ? den : bd;
                acc = fmaxf(acc, fmaf(7.0f, inter, s_mga3[t]));
            }
            float miou = bi / bd;

            // coord loss
            float4 tb = s_tb[tid];
            float d0 = P.sx - tb.x, d1 = P.sy - tb.y;
            float d2 = P.ew - tb.z, d3 = P.eh - tb.w;
            float asg = 0.5f * (d0 * d0 + d1 * d1 + d2 * d2 + d3 * d3);
            // objectness
            float di = OBJ_SCALE * P.conf - OBJ_SCALE * miou;
            asg += 0.5f * di * di;
            // class CE
            const float* p = ob + (size_t)(a * CH) * KK + k;
            float lmax = -1e30f;
            #pragma unroll
            for (int c = 0; c < NCLS; c++) lmax = fmaxf(lmax, p[(5 + c) * KK]);
            float se = 0.0f;
            #pragma unroll
            for (int c = 0; c < NCLS; c++) se += __expf(p[(5 + c) * KK] - lmax);
            asg += (lmax + __logf(se)) - p[(5 + s_cls[tid]) * KK];

            r2 = asg;
            // corrections: remove this anchor's noobj contributions
            r0 = -P.c2;
            if (acc >= P.pa3) r1 = -P.c2;
        }
    }

    // ---- block reduction (deterministic within block) ----
    #pragma unroll
    for (int o = 16; o > 0; o >>= 1) {
        r0 += __shfl_down_sync(0xffffffffu, r0, o);
        r1 += __shfl_down_sync(0xffffffffu, r1, o);
        r2 += __shfl_down_sync(0xffffffffu, r2, o);
        r3 += __shfl_down_sync(0xffffffffu, r3, o);
    }
    __shared__ float rA[THR / 32], rBs[THR / 32], rG[THR / 32], rP[THR / 32];
    int w = tid >> 5, l = tid & 31;
    if (l == 0) { rA[w] = r0; rBs[w] = r1; rG[w] = r2; rP[w] = r3; }
    __syncthreads();
    if (tid == 0) {
        float a0 = 0, b0 = 0, g0 = 0, p0 = 0;
        #pragma unroll
        for (int i = 0; i < THR / 32; i++) {
            a0 += rA[i]; b0 += rBs[i]; g0 += rG[i]; p0 += rP[i];
        }
        g_part[b][part] = make_float4(a0, b0, g0, p0);
    }
}

// ---------------------------------------------------------------------------
__global__ __launch_bounds__(BB)
void finalize(float* __restrict__ out) {
    const int b = threadIdx.x;
    float sA = 0, sB = 0, sG = 0, sP = 0;
    #pragma unroll
    for (int p = 0; p < PARTS + 1; p++) {
        float4 v = g_part[b][p];
        sA += v.x; sB += v.y; sG += v.z; sP += v.w;
    }
    bool pos = sP > 0.0f;
    float loss = 0.5f * (sA - (pos ? sB : 0.0f)) + sG;

    __shared__ float red[BB];
    red[b] = loss;
    __syncthreads();
    #pragma unroll
    for (int s = BB / 2; s > 0; s >>= 1) {
        if (b < s) red[b] += red[b + s];
        __syncthreads();
    }
    if (b == 0) out[0] = red[0] / (float)BB;
}

// ---------------------------------------------------------------------------
extern "C" void kernel_launch(void* const* d_in, const int* in_sizes, int n_in,
                              void* d_out, int out_size) {
    const float* outputs = (const float*)d_in[0];
    const float* targets = (const float*)d_in[1];
    if (n_in >= 2 && in_sizes[0] < in_sizes[1]) {
        outputs = (const float*)d_in[1];
        targets = (const float*)d_in[0];
    }
    float* out = (float*)d_out;

    dim3 grid(BB, PARTS + 1);
    mainKernel<<<grid, THR>>>(outputs, targets);
    finalize<<<1, BB>>>(out);
}